// round 16
// baseline (speedup 1.0000x reference)
#include <cuda_runtime.h>
#include <cuda_bf16.h>

#define T_DIM 512
#define B_DIM 128
#define E_DIM 256
#define KMAX  512

// Scratch (__device__ globals: allocation-free). All [t][b] transposed so the
// walk kernel (lanes = consecutive b, same t) is fully coalesced.
__device__ float g_Cpt[T_DIM * B_DIM];                // prefix of (d-u), [t][b]
__device__ float g_Mt [T_DIM * B_DIM];                // M_t = d_t - Cp_t, [t][b]
__device__ float g_bc [(size_t)T_DIM * KMAX * B_DIM]; // coeffs [t][k][b]
__device__ int   g_nb [T_DIM * B_DIM];                // band length [t][b]

// ---------------------------------------------------------------------------
// Kernel 1: per-batch inclusive prefix sum of (d - u); emit transposed Cp, M.
// ---------------------------------------------------------------------------
__global__ __launch_bounds__(T_DIM) void prefix_kernel(
    const float* __restrict__ u, const float* __restrict__ d) {
  const int b = blockIdx.x, tid = threadIdx.x;
  __shared__ float s[T_DIM];
  const float dt = d[tid * B_DIM + b];
  s[tid] = dt - u[tid * B_DIM + b];
  __syncthreads();
  #pragma unroll
  for (int off = 1; off < T_DIM; off <<= 1) {
    float o = (tid >= off) ? s[tid - off] : 0.f;
    __syncthreads();
    s[tid] += o;
    __syncthreads();
  }
  const float Cp = s[tid];
  g_Cpt[tid * B_DIM + b] = Cp;
  g_Mt [tid * B_DIM + b] = dt - Cp;
}

// ---------------------------------------------------------------------------
// Kernel 2: coefficient walk. Block = one t, 128 threads = all b. Per k step
// every lane reads M_t[j*B+b] and stores g_bc[(t*KMAX+k)*B+b]: both fully
// coalesced (j,k warp-uniform).
//   coeff_k = min(Cp_t + runmax_{j=t-k..t} M_j, 1) - prev;  stop at pc >= 1
// (running max monotone => all deeper coeffs exactly 0).
// ---------------------------------------------------------------------------
__global__ __launch_bounds__(B_DIM) void walk_kernel() {
  const int t = blockIdx.x;
  const int b = threadIdx.x;

  const float Cpt = g_Cpt[t * B_DIM + b];
  float* __restrict__ col = &g_bc[(size_t)t * KMAX * B_DIM + b];

  float rm = -3.4e38f, prev = 0.f;
  int nb = t + 1;
  bool done = false;
  for (int k = 0; k <= t; ++k) {
    if (!done) {
      rm = fmaxf(rm, __ldg(&g_Mt[(t - k) * B_DIM + b]));
      const float pc = fminf(Cpt + rm, 1.f);
      col[(size_t)k * B_DIM] = pc - prev;
      prev = pc;
      if (pc >= 1.f) { nb = k + 1; done = true; }
    }
    // warp exits when all 32 lanes are done
    if (__all_sync(0xffffffffu, done)) break;
  }
  g_nb[t * B_DIM + b] = nb;
}

// ---------------------------------------------------------------------------
// Kernel 3: banded read (round-3 proven form). 128-thread block covers two
// (t,b) rows: threadIdx.y in {0,1} selects t. 64 lanes x float4 over E.
// Coefficient loads are warp-uniform broadcasts; unconditional loads let
// consecutive k iterations pipeline.
// ---------------------------------------------------------------------------
__global__ __launch_bounds__(128) void read_kernel(
    const float* __restrict__ v, float* __restrict__ out) {
  const int t  = blockIdx.x * 2 + threadIdx.y;
  const int b  = blockIdx.y;
  const int e4 = threadIdx.x;                 // 64 lanes * 4 floats = 256

  const int nb = g_nb[t * B_DIM + b];
  const float* __restrict__ bccol = &g_bc[(size_t)t * KMAX * B_DIM + b];

  const float4* __restrict__ vb =
      (const float4*)(v + (size_t)b * E_DIM) + e4;
  const size_t row4 = (size_t)B_DIM * E_DIM / 4;

  float4 acc = make_float4(0.f, 0.f, 0.f, 0.f);
  #pragma unroll 2
  for (int k = 0; k < nb; ++k) {
    const float c = __ldg(bccol + (size_t)k * B_DIM);   // uniform broadcast
    const float4 vv = vb[(size_t)(t - k) * row4];
    acc.x = fmaf(c, vv.x, acc.x);
    acc.y = fmaf(c, vv.y, acc.y);
    acc.z = fmaf(c, vv.z, acc.z);
    acc.w = fmaf(c, vv.w, acc.w);
  }
  ((float4*)out)[((size_t)t * B_DIM + b) * (E_DIM / 4) + e4] = acc;
}

// ---------------------------------------------------------------------------
// Inputs: v [T,B,E] f32, u [T,B] f32, d [T,B] f32. Output: reads [T,B,E] f32.
// ---------------------------------------------------------------------------
extern "C" void kernel_launch(void* const* d_in, const int* in_sizes, int n_in,
                              void* d_out, int out_size) {
  const float* v = (const float*)d_in[0];
  const float* u = (const float*)d_in[1];
  const float* d = (const float*)d_in[2];
  float* out = (float*)d_out;

  prefix_kernel<<<B_DIM, T_DIM>>>(u, d);
  walk_kernel<<<T_DIM, B_DIM>>>();

  dim3 grid(T_DIM / 2, B_DIM);
  dim3 blk(64, 2);
  read_kernel<<<grid, blk>>>(v, out);
}